// round 8
// baseline (speedup 1.0000x reference)
#include <cuda_runtime.h>
#include <cuda_fp16.h>
#include <math.h>

#define N_NODES 20000
#define N_EDGES 320000
#define TOT_EDGES (N_EDGES + N_NODES)
#define SMEM_BYTES 60800

// ---------------- scratch ----------------
__device__ float  g_hA[N_NODES * 64];
__device__ float  g_hB[N_NODES * 64];
__device__ __half g_hproj[N_NODES * 256];
__device__ float  g_asrc[N_NODES * 4];
__device__ float  g_adst[N_NODES * 4];
__device__ int    g_deg[N_NODES];
__device__ int    g_off[N_NODES + 1];
__device__ int    g_cursor[N_NODES];
__device__ int    g_srcs[TOT_EDGES];
__device__ unsigned long long g_scanpk[80];
__device__ unsigned g_count = 0;
__device__ unsigned g_gen = 0;

__device__ __forceinline__ float eluf(float x) { return x > 0.f ? x : (__expf(x) - 1.f); }
__device__ __forceinline__ float lrelu(float x) { return x > 0.f ? x : 0.2f * x; }

__device__ __forceinline__ unsigned long long pack2(float a, float b) {
    unsigned long long r;
    asm("mov.b64 %0,{%1,%2};" : "=l"(r) : "f"(a), "f"(b));
    return r;
}
__device__ __forceinline__ float2 unpk2(unsigned long long v) {
    float2 r;
    asm("mov.b64 {%0,%1},%2;" : "=f"(r.x), "=f"(r.y) : "l"(v));
    return r;
}
__device__ __forceinline__ void fma2(unsigned long long& d, unsigned long long a, unsigned long long b) {
    asm("fma.rn.f32x2 %0,%1,%2,%0;" : "+l"(d) : "l"(a), "l"(b));
}
__device__ __forceinline__ unsigned long long add2(unsigned long long a, unsigned long long b) {
    unsigned long long r;
    asm("add.rn.f32x2 %0,%1,%2;" : "=l"(r) : "l"(a), "l"(b));
    return r;
}
__device__ __forceinline__ void st_rel64(unsigned long long* p, unsigned long long v) {
    asm volatile("st.release.gpu.global.u64 [%0],%1;" :: "l"(p), "l"(v) : "memory");
}
__device__ __forceinline__ unsigned long long ld_acq64(const unsigned long long* p) {
    unsigned long long v;
    asm volatile("ld.acquire.gpu.global.u64 %0,[%1];" : "=l"(v) : "l"(p));
    return v;
}

// ---------------- device-wide software barrier ----------------
__device__ __forceinline__ void gbar(int nb) {
    __syncthreads();
    if (threadIdx.x == 0) {
        unsigned my;
        asm volatile("ld.acquire.gpu.global.u32 %0,[%1];" : "=r"(my) : "l"(&g_gen));
        __threadfence();
        unsigned old = atomicAdd(&g_count, 1);
        if (old == (unsigned)(nb - 1)) {
            g_count = 0;
            __threadfence();
            asm volatile("red.release.gpu.global.add.u32 [%0],1;" :: "l"(&g_gen) : "memory");
        } else {
            unsigned cur;
            do {
                __nanosleep(64);
                asm volatile("ld.acquire.gpu.global.u32 %0,[%1];" : "=r"(cur) : "l"(&g_gen));
            } while (cur == my);
        }
    }
    __syncthreads();
}

// ---------------- GEMM core + fused attention-coefficient epilogue ----------------
// block tile: 64 rows x 128 cols, 256 threads, thread = 8 rows x 4 cols (f32x2)
__device__ __forceinline__ void gemm_core_and_att(
    int row0, int colbase, float* sW, float* sXT, float* sAs, float* sAd)
{
    int cg = threadIdx.x & 31;
    int rg = threadIdx.x >> 5;
    int c0 = cg * 4, r0 = rg * 8;
    unsigned long long acc[4][4];
#pragma unroll
    for (int a = 0; a < 4; a++)
#pragma unroll
        for (int b = 0; b < 4; b++) acc[a][b] = 0ull;
    unsigned xb = (unsigned)__cvta_generic_to_shared(&sXT[r0]);
#pragma unroll 4
    for (int k = 0; k < 64; k++) {
        unsigned long long xp[4];
        asm("ld.shared.v2.u64 {%0,%1},[%2];" : "=l"(xp[0]), "=l"(xp[1]) : "r"(xb + k * 272));
        asm("ld.shared.v2.u64 {%0,%1},[%2];" : "=l"(xp[2]), "=l"(xp[3]) : "r"(xb + k * 272 + 16));
        float4 wv = *(float4*)&sW[k * 128 + c0];
        unsigned long long wd[4] = {pack2(wv.x, wv.x), pack2(wv.y, wv.y),
                                    pack2(wv.z, wv.z), pack2(wv.w, wv.w)};
#pragma unroll
        for (int rp = 0; rp < 4; rp++)
#pragma unroll
            for (int c = 0; c < 4; c++) fma2(acc[rp][c], xp[rp], wd[c]);
    }

    // store fp16 hproj
#pragma unroll
    for (int rp = 0; rp < 4; rp++) {
        float2 f0 = unpk2(acc[rp][0]), f1 = unpk2(acc[rp][1]);
        float2 f2 = unpk2(acc[rp][2]), f3 = unpk2(acc[rp][3]);
        int rA = row0 + r0 + 2 * rp;
        if (rA < N_NODES) {
            __half2 a = __floats2half2_rn(f0.x, f1.x), b = __floats2half2_rn(f2.x, f3.x);
            uint2 st;
            st.x = *(unsigned*)&a;
            st.y = *(unsigned*)&b;
            *(uint2*)&g_hproj[(long long)rA * 256 + colbase + c0] = st;
        }
        if (rA + 1 < N_NODES) {
            __half2 a = __floats2half2_rn(f0.y, f1.y), b = __floats2half2_rn(f2.y, f3.y);
            uint2 st;
            st.x = *(unsigned*)&a;
            st.y = *(unsigned*)&b;
            *(uint2*)&g_hproj[(long long)(rA + 1) * 256 + colbase + c0] = st;
        }
    }

    // fused attention coefficients (2 heads per 128-col block)
    int headLocal = cg >> 4;
    int chBase = c0 & 63;
    float asv[4], adv[4];
#pragma unroll
    for (int c = 0; c < 4; c++) {
        asv[c] = sAs[headLocal * 64 + chBase + c];
        adv[c] = sAd[headLocal * 64 + chBase + c];
    }
    unsigned long long ps[4], pd[4];
#pragma unroll
    for (int rp = 0; rp < 4; rp++) { ps[rp] = 0ull; pd[rp] = 0ull; }
#pragma unroll
    for (int rp = 0; rp < 4; rp++)
#pragma unroll
        for (int c = 0; c < 4; c++) {
            fma2(ps[rp], acc[rp][c], pack2(asv[c], asv[c]));
            fma2(pd[rp], acc[rp][c], pack2(adv[c], adv[c]));
        }
#pragma unroll
    for (int o = 1; o < 16; o <<= 1) {
#pragma unroll
        for (int rp = 0; rp < 4; rp++) {
            ps[rp] = add2(ps[rp], __shfl_xor_sync(0xffffffffu, ps[rp], o));
            pd[rp] = add2(pd[rp], __shfl_xor_sync(0xffffffffu, pd[rp], o));
        }
    }
    if ((cg & 15) == 0) {
        int hg = (colbase >> 6) + headLocal;
#pragma unroll
        for (int rp = 0; rp < 4; rp++) {
            int rA = row0 + r0 + 2 * rp;
            float2 v = unpk2(ps[rp]);
            float2 w = unpk2(pd[rp]);
            if (rA < N_NODES) { g_asrc[rA * 4 + hg] = v.x; g_adst[rA * 4 + hg] = w.x; }
            if (rA + 1 < N_NODES) { g_asrc[(rA + 1) * 4 + hg] = v.y; g_adst[(rA + 1) * 4 + hg] = w.y; }
        }
    }
}

// ---------------- GEMM phase (layers 2,3): hin from global ----------------
__device__ void gemm_phase(const float* __restrict__ hin, const float* __restrict__ W,
                           const float* __restrict__ as_, const float* __restrict__ ad_,
                           char* smem, int G)
{
    float* sW = (float*)smem;
    float* sXT = (float*)(smem + 32768);
    float* sAs = (float*)(smem + 50176);
    float* sAd = (float*)(smem + 50688);
    for (int t = blockIdx.x; t < 626; t += G) {
        int row0 = (t >> 1) * 64, colbase = (t & 1) * 128;
        __syncthreads();
        for (int i = threadIdx.x; i < 2048; i += 256) {
            int k = i >> 5, c4 = (i & 31) * 4;
            *(float4*)&sW[k * 128 + c4] = *(const float4*)&W[k * 256 + colbase + c4];
        }
        if (threadIdx.x < 128) {
            sAs[threadIdx.x] = as_[colbase + threadIdx.x];
            sAd[threadIdx.x] = ad_[colbase + threadIdx.x];
        }
        for (int i = threadIdx.x; i < 1024; i += 256) {
            int r = i >> 4, k0 = (i & 15) * 4;
            float4 v = make_float4(0.f, 0.f, 0.f, 0.f);
            if (row0 + r < N_NODES) v = *(const float4*)&hin[(row0 + r) * 64 + k0];
            sXT[(k0 + 0) * 68 + r] = v.x;
            sXT[(k0 + 1) * 68 + r] = v.y;
            sXT[(k0 + 2) * 68 + r] = v.z;
            sXT[(k0 + 3) * 68 + r] = v.w;
        }
        __syncthreads();
        gemm_core_and_att(row0, colbase, sW, sXT, sAs, sAd);
    }
}

// ---------------- aggregation phase: warp-strided over dst nodes ----------------
__device__ void agg_phase(const float* __restrict__ bias,
                          const float* __restrict__ hin, float* __restrict__ hout,
                          char* smem, int G)
{
    int wib = threadIdx.x >> 5;
    int lane = threadIdx.x & 31;
    int* ss = (int*)smem + wib * 32;
    float* se = (float*)(smem + 1024) + wib * 128;
    int head = lane >> 3;
    const uint4* hp4 = (const uint4*)g_hproj;
    int nw = G * 8;
    for (int d = blockIdx.x * 8 + wib; d < N_NODES; d += nw) {
        int start = g_off[d], end = g_off[d + 1];
        float4 adst = *(const float4*)(g_adst + d * 4);

        float m0 = -1e30f, m1 = -1e30f, m2 = -1e30f, m3 = -1e30f;
        for (int i = start + lane; i < end; i += 32) {
            int s = g_srcs[i];
            float4 a = *(const float4*)(g_asrc + s * 4);
            m0 = fmaxf(m0, lrelu(a.x + adst.x));
            m1 = fmaxf(m1, lrelu(a.y + adst.y));
            m2 = fmaxf(m2, lrelu(a.z + adst.z));
            m3 = fmaxf(m3, lrelu(a.w + adst.w));
        }
#pragma unroll
        for (int o = 16; o; o >>= 1) {
            m0 = fmaxf(m0, __shfl_xor_sync(0xffffffffu, m0, o));
            m1 = fmaxf(m1, __shfl_xor_sync(0xffffffffu, m1, o));
            m2 = fmaxf(m2, __shfl_xor_sync(0xffffffffu, m2, o));
            m3 = fmaxf(m3, __shfl_xor_sync(0xffffffffu, m3, o));
        }

        unsigned long long acc2[4] = {0ull, 0ull, 0ull, 0ull};
        float den0 = 0.f, den1 = 0.f, den2 = 0.f, den3 = 0.f;
        for (int base = start; base < end; base += 32) {
            int i = base + lane;
            int cnt = min(32, end - base);
            if (i < end) {
                int s = g_srcs[i];
                float4 a = *(const float4*)(g_asrc + s * 4);
                float e0 = __expf(lrelu(a.x + adst.x) - m0);
                float e1 = __expf(lrelu(a.y + adst.y) - m1);
                float e2 = __expf(lrelu(a.z + adst.z) - m2);
                float e3 = __expf(lrelu(a.w + adst.w) - m3);
                den0 += e0; den1 += e1; den2 += e2; den3 += e3;
                ss[lane] = s;
                se[lane * 4 + 0] = e0;
                se[lane * 4 + 1] = e1;
                se[lane * 4 + 2] = e2;
                se[lane * 4 + 3] = e3;
            }
            __syncwarp();
#pragma unroll 2
            for (int k = 0; k < cnt; k++) {
                int s = ss[k];
                float eh = se[k * 4 + head];
                unsigned long long ep = pack2(eh, eh);
                uint4 raw = __ldg(&hp4[(long long)s * 32 + lane]);
                float2 q0 = __half22float2(*(__half2*)&raw.x);
                float2 q1 = __half22float2(*(__half2*)&raw.y);
                float2 q2 = __half22float2(*(__half2*)&raw.z);
                float2 q3 = __half22float2(*(__half2*)&raw.w);
                fma2(acc2[0], ep, pack2(q0.x, q0.y));
                fma2(acc2[1], ep, pack2(q1.x, q1.y));
                fma2(acc2[2], ep, pack2(q2.x, q2.y));
                fma2(acc2[3], ep, pack2(q3.x, q3.y));
            }
            __syncwarp();
        }

#pragma unroll
        for (int o = 16; o; o >>= 1) {
            den0 += __shfl_xor_sync(0xffffffffu, den0, o);
            den1 += __shfl_xor_sync(0xffffffffu, den1, o);
            den2 += __shfl_xor_sync(0xffffffffu, den2, o);
            den3 += __shfl_xor_sync(0xffffffffu, den3, o);
        }
        float dh = (head == 0) ? den0 : (head == 1) ? den1 : (head == 2) ? den2 : den3;
        float inv = 1.f / (dh + 1e-16f);
        float acc[8];
#pragma unroll
        for (int j = 0; j < 4; j++) {
            float2 f = unpk2(acc2[j]);
            acc[2 * j] = f.x * inv;
            acc[2 * j + 1] = f.y * inv;
        }
#pragma unroll
        for (int j = 0; j < 8; j++) {
            acc[j] += __shfl_xor_sync(0xffffffffu, acc[j], 8);
            acc[j] += __shfl_xor_sync(0xffffffffu, acc[j], 16);
        }
        if (lane < 8) {
#pragma unroll
            for (int j = 0; j < 8; j++) {
                int cc = lane * 8 + j;
                hout[d * 64 + cc] = 0.25f * acc[j] + bias[cc] + hin[d * 64 + cc];
            }
        }
    }
}

// ================= THE megakernel =================
extern "C" __global__ void __launch_bounds__(256) k_mega(
    const float* __restrict__ x, const void* __restrict__ ei,
    const float* __restrict__ We1, const float* __restrict__ be1,
    const float* __restrict__ We2, const float* __restrict__ be2,
    const float* __restrict__ Wg1, const float* __restrict__ as1,
    const float* __restrict__ ad1, const float* __restrict__ bg1,
    const float* __restrict__ Wg2, const float* __restrict__ as2,
    const float* __restrict__ ad2, const float* __restrict__ bg2,
    const float* __restrict__ Wg3, const float* __restrict__ as3,
    const float* __restrict__ ad3, const float* __restrict__ bg3,
    const float* __restrict__ Wo1, const float* __restrict__ bo1,
    const float* __restrict__ Wo2, const float* __restrict__ bo2,
    const float* __restrict__ Wo3, const float* __restrict__ bo3,
    float* __restrict__ out, int G)
{
    extern __shared__ char smem[];
    __shared__ int swsum[8];
    __shared__ int s_prefix;
    int tid = threadIdx.x;
    int bid = blockIdx.x;

    // ---- P0: per-block dtype detect + zero deg + zero scan state ----
    const int* eiw = (const int*)ei;
    int found = 0;
    for (int j = 1 + 2 * tid; j < 2048; j += 512)
        if (eiw[j] != 0) found = 1;
    int is64 = __syncthreads_or(found) ? 0 : 1;
    for (int i = bid * 256 + tid; i < N_NODES; i += G * 256) g_deg[i] = 0;
    if (bid == 0 && tid < 80) g_scanpk[tid] = 0ull;
    gbar(G);

    // ---- P1: edge count  +  fused encoder + layer-1 GEMM + att ----
    {
        float* sW = (float*)smem;
        float* sXT = (float*)(smem + 32768);
        float* sAs = (float*)(smem + 50176);
        float* sAd = (float*)(smem + 50688);
        float* sE1 = (float*)(smem + 51200);
        float* sB1 = (float*)(smem + 52224);
        float* sE2 = (float*)(smem + 52352);
        float* sB2 = (float*)(smem + 60544);

        for (int e = bid * 256 + tid; e < N_EDGES; e += G * 256) {
            int dd = is64 ? (int)((const long long*)ei)[N_EDGES + e] : ((const int*)ei)[N_EDGES + e];
            atomicAdd(&g_deg[dd], 1);
        }
        for (int i = tid; i < 256; i += 256) sE1[i] = We1[i];
        if (tid < 32) sB1[tid] = be1[tid];
        for (int i = tid; i < 2048; i += 256) sE2[i] = We2[i];
        if (tid < 64) sB2[tid] = be2[tid];

        for (int t = bid; t < 626; t += G) {
            int row0 = (t >> 1) * 64, colbase = (t & 1) * 128;
            __syncthreads();
            for (int i = tid; i < 2048; i += 256) {
                int k = i >> 5, c4 = (i & 31) * 4;
                *(float4*)&sW[k * 128 + c4] = *(const float4*)&Wg1[k * 256 + colbase + c4];
            }
            if (tid < 128) {
                sAs[tid] = as1[colbase + tid];
                sAd[tid] = ad1[colbase + tid];
            }
            // encoder for 64 rows: thread = (row, quarter)
            {
                int rr = tid >> 2;
                int q = tid & 3;
                int n = row0 + rr;
                float outv[16];
                if (n < N_NODES) {
                    float4 xa = *(const float4*)&x[n * 8];
                    float4 xb = *(const float4*)&x[n * 8 + 4];
                    float xi[8] = {xa.x, xa.y, xa.z, xa.w, xb.x, xb.y, xb.z, xb.w};
                    float hid[32];
#pragma unroll
                    for (int j = 0; j < 32; j++) {
                        float a = sB1[j];
#pragma unroll
                        for (int i = 0; i < 8; i++) a += xi[i] * sE1[i * 32 + j];
                        hid[j] = eluf(a);
                    }
#pragma unroll
                    for (int j = 0; j < 16; j++) {
                        int jj = q * 16 + j;
                        float a = sB2[jj];
#pragma unroll
                        for (int i = 0; i < 32; i++) a += hid[i] * sE2[i * 64 + jj];
                        outv[j] = eluf(a);
                    }
                } else {
#pragma unroll
                    for (int j = 0; j < 16; j++) outv[j] = 0.f;
                }
#pragma unroll
                for (int j = 0; j < 16; j++) sXT[(q * 16 + j) * 68 + rr] = outv[j];
                if (colbase == 0 && n < N_NODES) {
#pragma unroll
                    for (int j = 0; j < 16; j += 4)
                        *(float4*)&g_hA[n * 64 + q * 16 + j] =
                            make_float4(outv[j], outv[j + 1], outv[j + 2], outv[j + 3]);
                }
            }
            __syncthreads();
            gemm_core_and_att(row0, colbase, sW, sXT, sAs, sAd);
        }
    }
    gbar(G);

    // ---- P2: decoupled-lookback scan of deg+1 ----
    {
        int i = bid * 256 + tid;
        if (bid < 79) {
            int v = (i < N_NODES) ? (g_deg[i] + 1) : 0;
            int lane = tid & 31, w = tid >> 5;
            int s = v;
#pragma unroll
            for (int o = 1; o < 32; o <<= 1) {
                int u = __shfl_up_sync(0xffffffffu, s, o);
                if (lane >= o) s += u;
            }
            if (lane == 31) swsum[w] = s;
            __syncthreads();
            if (w == 0 && lane < 8) {
                int xv = swsum[lane];
#pragma unroll
                for (int o = 1; o < 8; o <<= 1) {
                    int u = __shfl_up_sync(0xffu, xv, o);
                    if (lane >= o) xv += u;
                }
                swsum[lane] = xv;
            }
            __syncthreads();
            int base = (w > 0) ? swsum[w - 1] : 0;
            int total = swsum[7];
            if (tid == 0) {
                int prefix = 0;
                if (bid == 0) {
                    st_rel64(&g_scanpk[0], (2ull << 32) | (unsigned)total);
                } else {
                    st_rel64(&g_scanpk[bid], (1ull << 32) | (unsigned)total);
                    int i2 = bid - 1;
                    while (i2 >= 0) {
                        unsigned long long pk = ld_acq64(&g_scanpk[i2]);
                        unsigned f = (unsigned)(pk >> 32);
                        if (f == 0) { __nanosleep(30); continue; }
                        prefix += (int)(unsigned)pk;
                        if (f == 2u) break;
                        i2--;
                    }
                    st_rel64(&g_scanpk[bid], (2ull << 32) | (unsigned)(prefix + total));
                }
                s_prefix = prefix;
            }
            __syncthreads();
            if (i < N_NODES) {
                int off = s_prefix + base + s - v;
                g_off[i] = off;
                g_cursor[i] = off;
            }
        }
        if (bid == 0 && tid == 0) g_off[N_NODES] = TOT_EDGES;
    }
    gbar(G);

    // ---- P3: scatter edges into CSR ----
    for (int e = bid * 256 + tid; e < TOT_EDGES; e += G * 256) {
        int s, d;
        if (e < N_EDGES) {
            if (is64) {
                s = (int)((const long long*)ei)[e];
                d = (int)((const long long*)ei)[N_EDGES + e];
            } else {
                s = ((const int*)ei)[e];
                d = ((const int*)ei)[N_EDGES + e];
            }
        } else {
            s = d = e - N_EDGES;
        }
        int p = atomicAdd(&g_cursor[d], 1);
        g_srcs[p] = s;
    }
    gbar(G);

    // ---- layers ----
    agg_phase(bg1, g_hA, g_hB, smem, G);
    gbar(G);
    gemm_phase(g_hB, Wg2, as2, ad2, smem, G);
    gbar(G);
    agg_phase(bg2, g_hB, g_hA, smem, G);
    gbar(G);
    gemm_phase(g_hA, Wg3, as3, ad3, smem, G);
    gbar(G);
    agg_phase(bg3, g_hA, g_hB, smem, G);
    gbar(G);

    // ---- P9: output MLP, warp-strided ----
    {
        float* sW1 = (float*)smem;
        float* sW2 = (float*)(smem + 16384);
        float* sW3 = (float*)(smem + 24576);
        float* sb1 = (float*)(smem + 25600);
        float* sb2 = (float*)(smem + 25856);
        float* sb3 = (float*)(smem + 25984);
        float* shh = (float*)(smem + 26112);
        float* sh1 = (float*)(smem + 28160);
        float* sh2 = (float*)(smem + 30208);
        for (int i = tid; i < 4096; i += 256) sW1[i] = Wo1[i];
        for (int i = tid; i < 2048; i += 256) sW2[i] = Wo2[i];
        if (tid < 256) sW3[tid] = Wo3[tid];
        if (tid < 64) sb1[tid] = bo1[tid];
        if (tid < 32) sb2[tid] = bo2[tid];
        if (tid < 8) sb3[tid] = bo3[tid];
        __syncthreads();
        int wib = tid >> 5;
        int lane = tid & 31;
        float* mh = shh + wib * 64;
        float* mh1 = sh1 + wib * 64;
        float* mh2 = sh2 + wib * 32;
        const float* hin = g_hB;
        int nw = G * 8;
        for (int d = bid * 8 + wib; d < N_NODES; d += nw) {
            mh[lane] = hin[d * 64 + lane];
            mh[lane + 32] = hin[d * 64 + lane + 32];
            __syncwarp();
            float a0 = sb1[lane], a1 = sb1[lane + 32];
#pragma unroll
            for (int i = 0; i < 64; i++) {
                float xv = mh[i];
                a0 += xv * sW1[i * 64 + lane];
                a1 += xv * sW1[i * 64 + lane + 32];
            }
            mh1[lane] = eluf(a0);
            mh1[lane + 32] = eluf(a1);
            __syncwarp();
            float a = sb2[lane];
#pragma unroll
            for (int i = 0; i < 64; i++) a += mh1[i] * sW2[i * 32 + lane];
            mh2[lane] = eluf(a);
            __syncwarp();
            if (lane < 8) {
                float o = sb3[lane];
#pragma unroll
                for (int i = 0; i < 32; i++) o += mh2[i] * sW3[i * 8 + lane];
                out[d * 8 + lane] = o;
            }
            __syncwarp();
        }
    }
}

// ---------------- launch ----------------
extern "C" void kernel_launch(void* const* d_in, const int* in_sizes, int n_in,
                              void* d_out, int out_size) {
    static bool inited = false;
    static int grid = 0;
    if (!inited) {
        cudaFuncSetAttribute(k_mega, cudaFuncAttributeMaxDynamicSharedMemorySize, SMEM_BYTES);
        int dev = 0;
        cudaGetDevice(&dev);
        int sms = 148;
        cudaDeviceGetAttribute(&sms, cudaDevAttrMultiProcessorCount, dev);
        int occ = 1;
        cudaOccupancyMaxActiveBlocksPerMultiprocessor(&occ, k_mega, 256, SMEM_BYTES);
        if (occ < 1) occ = 1;
        if (occ > 3) occ = 3;
        grid = sms * occ;
        inited = true;
    }

    k_mega<<<grid, 256, SMEM_BYTES, 0>>>(
        (const float*)d_in[0], d_in[1],
        (const float*)d_in[2], (const float*)d_in[3],
        (const float*)d_in[4], (const float*)d_in[5],
        (const float*)d_in[6], (const float*)d_in[7],
        (const float*)d_in[8], (const float*)d_in[9],
        (const float*)d_in[10], (const float*)d_in[11],
        (const float*)d_in[12], (const float*)d_in[13],
        (const float*)d_in[14], (const float*)d_in[15],
        (const float*)d_in[16], (const float*)d_in[17],
        (const float*)d_in[18], (const float*)d_in[19],
        (const float*)d_in[20], (const float*)d_in[21],
        (const float*)d_in[22], (const float*)d_in[23],
        (float*)d_out, grid);

    (void)in_sizes; (void)n_in; (void)out_size;
}

// round 13
// speedup vs baseline: 2.0818x; 2.0818x over previous
#include <cuda_runtime.h>
#include <cuda_fp16.h>
#include <math.h>

#define N_NODES 20000
#define N_EDGES 320000
#define TOT_EDGES (N_EDGES + N_NODES)
#define NB_SCAN 79

// ---------------- scratch ----------------
__device__ float  g_hA[N_NODES * 64];
__device__ float  g_hB[N_NODES * 64];
__device__ __half g_hproj[N_NODES * 256];
__device__ float  g_asrc[N_NODES * 4];
__device__ float  g_adst[N_NODES * 4];
// deg histogram + scan-lookback state, zeroed together by one memset
__device__ int    g_deg[N_NODES + 160];
__device__ int    g_off[N_NODES + 1];
__device__ int    g_cursor[N_NODES];
__device__ int    g_srcs[TOT_EDGES];

__device__ __forceinline__ float eluf(float x) { return x > 0.f ? x : (__expf(x) - 1.f); }
__device__ __forceinline__ float lrelu(float x) { return x > 0.f ? x : 0.2f * x; }

__device__ __forceinline__ unsigned long long pack2(float a, float b) {
    unsigned long long r;
    asm("mov.b64 %0,{%1,%2};" : "=l"(r) : "f"(a), "f"(b));
    return r;
}
__device__ __forceinline__ float2 unpk2(unsigned long long v) {
    float2 r;
    asm("mov.b64 {%0,%1},%2;" : "=f"(r.x), "=f"(r.y) : "l"(v));
    return r;
}
__device__ __forceinline__ void fma2(unsigned long long& d, unsigned long long a, unsigned long long b) {
    asm("fma.rn.f32x2 %0,%1,%2,%0;" : "+l"(d) : "l"(a), "l"(b));
}
__device__ __forceinline__ unsigned long long add2(unsigned long long a, unsigned long long b) {
    unsigned long long r;
    asm("add.rn.f32x2 %0,%1,%2;" : "=l"(r) : "l"(a), "l"(b));
    return r;
}
__device__ __forceinline__ void st_rel64(unsigned long long* p, unsigned long long v) {
    asm volatile("st.release.gpu.global.u64 [%0],%1;" :: "l"(p), "l"(v) : "memory");
}
__device__ __forceinline__ unsigned long long ld_acq64(const unsigned long long* p) {
    unsigned long long v;
    asm volatile("ld.acquire.gpu.global.u64 %0,[%1];" : "=l"(v) : "l"(p));
    return v;
}

// per-block edge-dtype detection (8KB read, L2-broadcast)
__device__ __forceinline__ int detect_is64(const void* ei) {
    const int* w = (const int*)ei;
    int found = 0;
    for (int j = 1 + 2 * threadIdx.x; j < 2048; j += 2 * blockDim.x)
        if (w[j] != 0) found = 1;
    return __syncthreads_or(found) ? 0 : 1;
}

// ---------------- CSR: count ----------------
__global__ void k_count(const void* ei) {
    int is64 = detect_is64(ei);
    int e = blockIdx.x * blockDim.x + threadIdx.x;
    if (e >= N_EDGES) return;
    int d = is64 ? (int)((const long long*)ei)[N_EDGES + e] : ((const int*)ei)[N_EDGES + e];
    atomicAdd(&g_deg[d], 1);
}

// ---------------- CSR: single-pass decoupled-lookback scan ----------------
__global__ void k_scan() {
    __shared__ int swsum[8];
    __shared__ int s_prefix;
    unsigned long long* scanpk = (unsigned long long*)&g_deg[N_NODES];
    int tid = threadIdx.x, bid = blockIdx.x;
    int i = bid * 256 + tid;
    int v = (i < N_NODES) ? (g_deg[i] + 1) : 0;  // +1 self loop
    int lane = tid & 31, w = tid >> 5;
    int s = v;
#pragma unroll
    for (int o = 1; o < 32; o <<= 1) {
        int u = __shfl_up_sync(0xffffffffu, s, o);
        if (lane >= o) s += u;
    }
    if (lane == 31) swsum[w] = s;
    __syncthreads();
    if (w == 0 && lane < 8) {
        int xv = swsum[lane];
#pragma unroll
        for (int o = 1; o < 8; o <<= 1) {
            int u = __shfl_up_sync(0xffu, xv, o);
            if (lane >= o) xv += u;
        }
        swsum[lane] = xv;
    }
    __syncthreads();
    int base = (w > 0) ? swsum[w - 1] : 0;
    int total = swsum[7];
    if (tid == 0) {
        int prefix = 0;
        if (bid == 0) {
            st_rel64(&scanpk[0], (2ull << 32) | (unsigned)total);
        } else {
            st_rel64(&scanpk[bid], (1ull << 32) | (unsigned)total);
            int i2 = bid - 1;
            while (i2 >= 0) {
                unsigned long long pk = ld_acq64(&scanpk[i2]);
                unsigned f = (unsigned)(pk >> 32);
                if (f == 0) { __nanosleep(30); continue; }
                prefix += (int)(unsigned)pk;
                if (f == 2u) break;
                i2--;
            }
            st_rel64(&scanpk[bid], (2ull << 32) | (unsigned)(prefix + total));
        }
        s_prefix = prefix;
        if (bid == 0) g_off[N_NODES] = TOT_EDGES;
    }
    __syncthreads();
    if (i < N_NODES) {
        int off = s_prefix + base + s - v;
        g_off[i] = off;
        g_cursor[i] = off;
    }
}

// ---------------- CSR: scatter ----------------
__global__ void k_scatter(const void* ei) {
    int is64 = detect_is64(ei);
    int e = blockIdx.x * blockDim.x + threadIdx.x;
    if (e >= TOT_EDGES) return;
    int s, d;
    if (e < N_EDGES) {
        if (is64) {
            s = (int)((const long long*)ei)[e];
            d = (int)((const long long*)ei)[N_EDGES + e];
        } else {
            s = ((const int*)ei)[e];
            d = ((const int*)ei)[N_EDGES + e];
        }
    } else {
        s = d = e - N_EDGES;
    }
    int p = atomicAdd(&g_cursor[d], 1);
    g_srcs[p] = s;
}

// =======================================================================
// GEMM core + fused attention-coefficient epilogue
// =======================================================================
__device__ __forceinline__ void gemm_core_and_att(
    int row0, int colbase, float* sW, float* sXT, float* sAs, float* sAd)
{
    int cg = threadIdx.x & 31;
    int rg = threadIdx.x >> 5;
    int c0 = cg * 4, r0 = rg * 8;
    unsigned long long acc[4][4];
#pragma unroll
    for (int a = 0; a < 4; a++)
#pragma unroll
        for (int b = 0; b < 4; b++) acc[a][b] = 0ull;
    unsigned xb = (unsigned)__cvta_generic_to_shared(&sXT[r0]);
#pragma unroll 4
    for (int k = 0; k < 64; k++) {
        unsigned long long xp[4];
        asm("ld.shared.v2.u64 {%0,%1},[%2];" : "=l"(xp[0]), "=l"(xp[1]) : "r"(xb + k * 272));
        asm("ld.shared.v2.u64 {%0,%1},[%2];" : "=l"(xp[2]), "=l"(xp[3]) : "r"(xb + k * 272 + 16));
        float4 wv = *(float4*)&sW[k * 128 + c0];
        unsigned long long wd[4] = {pack2(wv.x, wv.x), pack2(wv.y, wv.y),
                                    pack2(wv.z, wv.z), pack2(wv.w, wv.w)};
#pragma unroll
        for (int rp = 0; rp < 4; rp++)
#pragma unroll
            for (int c = 0; c < 4; c++) fma2(acc[rp][c], xp[rp], wd[c]);
    }

#pragma unroll
    for (int rp = 0; rp < 4; rp++) {
        float2 f0 = unpk2(acc[rp][0]), f1 = unpk2(acc[rp][1]);
        float2 f2 = unpk2(acc[rp][2]), f3 = unpk2(acc[rp][3]);
        int rA = row0 + r0 + 2 * rp;
        if (rA < N_NODES) {
            __half2 a = __floats2half2_rn(f0.x, f1.x), b = __floats2half2_rn(f2.x, f3.x);
            uint2 st;
            st.x = *(unsigned*)&a;
            st.y = *(unsigned*)&b;
            *(uint2*)&g_hproj[(long long)rA * 256 + colbase + c0] = st;
        }
        if (rA + 1 < N_NODES) {
            __half2 a = __floats2half2_rn(f0.y, f1.y), b = __floats2half2_rn(f2.y, f3.y);
            uint2 st;
            st.x = *(unsigned*)&a;
            st.y = *(unsigned*)&b;
            *(uint2*)&g_hproj[(long long)(rA + 1) * 256 + colbase + c0] = st;
        }
    }

    int headLocal = cg >> 4;
    int chBase = c0 & 63;
    float asv[4], adv[4];
#pragma unroll
    for (int c = 0; c < 4; c++) {
        asv[c] = sAs[headLocal * 64 + chBase + c];
        adv[c] = sAd[headLocal * 64 + chBase + c];
    }
    unsigned long long ps[4], pd[4];
#pragma unroll
    for (int rp = 0; rp < 4; rp++) { ps[rp] = 0ull; pd[rp] = 0ull; }
#pragma unroll
    for (int rp = 0; rp < 4; rp++)
#pragma unroll
        for (int c = 0; c < 4; c++) {
            fma2(ps[rp], acc[rp][c], pack2(asv[c], asv[c]));
            fma2(pd[rp], acc[rp][c], pack2(adv[c], adv[c]));
        }
#pragma unroll
    for (int o = 1; o < 16; o <<= 1) {
#pragma unroll
        for (int rp = 0; rp < 4; rp++) {
            ps[rp] = add2(ps[rp], __shfl_xor_sync(0xffffffffu, ps[rp], o));
            pd[rp] = add2(pd[rp], __shfl_xor_sync(0xffffffffu, pd[rp], o));
        }
    }
    if ((cg & 15) == 0) {
        int hg = (colbase >> 6) + headLocal;
#pragma unroll
        for (int rp = 0; rp < 4; rp++) {
            int rA = row0 + r0 + 2 * rp;
            float2 v = unpk2(ps[rp]);
            float2 w = unpk2(pd[rp]);
            if (rA < N_NODES) { g_asrc[rA * 4 + hg] = v.x; g_adst[rA * 4 + hg] = w.x; }
            if (rA + 1 < N_NODES) { g_asrc[(rA + 1) * 4 + hg] = v.y; g_adst[(rA + 1) * 4 + hg] = w.y; }
        }
    }
}

// layers 2,3
__global__ void __launch_bounds__(256) k_gemm_att(
    const float* __restrict__ hin, const float* __restrict__ W,
    const float* __restrict__ as_, const float* __restrict__ ad_)
{
    __shared__ float sW[64 * 128];
    __shared__ float sXT[64 * 68];
    __shared__ float sAs[128], sAd[128];
    int row0 = blockIdx.x * 64;
    int colbase = blockIdx.y * 128;
    for (int i = threadIdx.x; i < 2048; i += 256) {
        int k = i >> 5, c4 = (i & 31) * 4;
        *(float4*)&sW[k * 128 + c4] = *(const float4*)&W[k * 256 + colbase + c4];
    }
    if (threadIdx.x < 128) {
        sAs[threadIdx.x] = as_[colbase + threadIdx.x];
        sAd[threadIdx.x] = ad_[colbase + threadIdx.x];
    }
    for (int i = threadIdx.x; i < 1024; i += 256) {
        int r = i >> 4, k0 = (i & 15) * 4;
        float4 v = make_float4(0.f, 0.f, 0.f, 0.f);
        if (row0 + r < N_NODES) v = *(const float4*)&hin[(row0 + r) * 64 + k0];
        sXT[(k0 + 0) * 68 + r] = v.x;
        sXT[(k0 + 1) * 68 + r] = v.y;
        sXT[(k0 + 2) * 68 + r] = v.z;
        sXT[(k0 + 3) * 68 + r] = v.w;
    }
    __syncthreads();
    gemm_core_and_att(row0, colbase, sW, sXT, sAs, sAd);
}

// layer 1: fused encoder
__global__ void __launch_bounds__(256) k_gemm_enc(
    const float* __restrict__ x,
    const float* __restrict__ We1, const float* __restrict__ be1,
    const float* __restrict__ We2, const float* __restrict__ be2,
    const float* __restrict__ W,
    const float* __restrict__ as_, const float* __restrict__ ad_,
    float* __restrict__ hA)
{
    __shared__ float sW[64 * 128];
    __shared__ float sXT[64 * 68];
    __shared__ float sAs[128], sAd[128];
    __shared__ float sE1[8 * 32], sB1[32], sE2[32 * 64], sB2[64];
    int row0 = blockIdx.x * 64;
    int colbase = blockIdx.y * 128;
    for (int i = threadIdx.x; i < 2048; i += 256) {
        int k = i >> 5, c4 = (i & 31) * 4;
        *(float4*)&sW[k * 128 + c4] = *(const float4*)&W[k * 256 + colbase + c4];
    }
    if (threadIdx.x < 128) {
        sAs[threadIdx.x] = as_[colbase + threadIdx.x];
        sAd[threadIdx.x] = ad_[colbase + threadIdx.x];
    }
    if (threadIdx.x < 256) sE1[threadIdx.x] = We1[threadIdx.x];
    if (threadIdx.x < 32) sB1[threadIdx.x] = be1[threadIdx.x];
    for (int i = threadIdx.x; i < 2048; i += 256) sE2[i] = We2[i];
    if (threadIdx.x < 64) sB2[threadIdx.x] = be2[threadIdx.x];
    __syncthreads();
    {
        int rr = threadIdx.x >> 2;
        int q = threadIdx.x & 3;
        int n = row0 + rr;
        float outv[16];
        if (n < N_NODES) {
            float4 xa = *(const float4*)&x[n * 8];
            float4 xb = *(const float4*)&x[n * 8 + 4];
            float xi[8] = {xa.x, xa.y, xa.z, xa.w, xb.x, xb.y, xb.z, xb.w};
            float hid[32];
#pragma unroll
            for (int j = 0; j < 32; j++) {
                float a = sB1[j];
#pragma unroll
                for (int i = 0; i < 8; i++) a += xi[i] * sE1[i * 32 + j];
                hid[j] = eluf(a);
            }
#pragma unroll
            for (int j = 0; j < 16; j++) {
                int jj = q * 16 + j;
                float a = sB2[jj];
#pragma unroll
                for (int i = 0; i < 32; i++) a += hid[i] * sE2[i * 64 + jj];
                outv[j] = eluf(a);
            }
        } else {
#pragma unroll
            for (int j = 0; j < 16; j++) outv[j] = 0.f;
        }
#pragma unroll
        for (int j = 0; j < 16; j++) sXT[(q * 16 + j) * 68 + rr] = outv[j];
        if (blockIdx.y == 0 && n < N_NODES) {
#pragma unroll
            for (int j = 0; j < 16; j += 4)
                *(float4*)&hA[n * 64 + q * 16 + j] =
                    make_float4(outv[j], outv[j + 1], outv[j + 2], outv[j + 3]);
        }
    }
    __syncthreads();
    gemm_core_and_att(row0, colbase, sW, sXT, sAs, sAd);
}

// ---------------- aggregation core (single pass, shift-free softmax) ----------------
// lanes 0-7 write the 64-channel result (with bias + residual) to dst64.
__device__ __forceinline__ void agg_node(
    int d, const float* __restrict__ bias, const float* __restrict__ hin,
    int* ss, float* se, float* dst64, int lane)
{
    int start = g_off[d], end = g_off[d + 1];
    float4 adst = *(const float4*)(g_adst + d * 4);
    int head = lane >> 3;
    unsigned long long acc2[4] = {0ull, 0ull, 0ull, 0ull};
    float den0 = 0.f, den1 = 0.f, den2 = 0.f, den3 = 0.f;
    const uint4* hp4 = (const uint4*)g_hproj;

    for (int base = start; base < end; base += 32) {
        int i = base + lane;
        int cnt = min(32, end - base);
        if (i < end) {
            int s = g_srcs[i];
            float4 a = *(const float4*)(g_asrc + s * 4);
            float e0 = __expf(lrelu(a.x + adst.x));
            float e1 = __expf(lrelu(a.y + adst.y));
            float e2 = __expf(lrelu(a.z + adst.z));
            float e3 = __expf(lrelu(a.w + adst.w));
            den0 += e0; den1 += e1; den2 += e2; den3 += e3;
            ss[lane] = s;
            se[lane * 4 + 0] = e0;
            se[lane * 4 + 1] = e1;
            se[lane * 4 + 2] = e2;
            se[lane * 4 + 3] = e3;
        }
        __syncwarp();
#pragma unroll 2
        for (int k = 0; k < cnt; k++) {
            int s = ss[k];
            float eh = se[k * 4 + head];
            unsigned long long ep = pack2(eh, eh);
            uint4 raw = __ldg(&hp4[(long long)s * 32 + lane]);
            float2 q0 = __half22float2(*(__half2*)&raw.x);
            float2 q1 = __half22float2(*(__half2*)&raw.y);
            float2 q2 = __half22float2(*(__half2*)&raw.z);
            float2 q3 = __half22float2(*(__half2*)&raw.w);
            fma2(acc2[0], ep, pack2(q0.x, q0.y));
            fma2(acc2[1], ep, pack2(q1.x, q1.y));
            fma2(acc2[2], ep, pack2(q2.x, q2.y));
            fma2(acc2[3], ep, pack2(q3.x, q3.y));
        }
        __syncwarp();
    }

#pragma unroll
    for (int o = 16; o; o >>= 1) {
        den0 += __shfl_xor_sync(0xffffffffu, den0, o);
        den1 += __shfl_xor_sync(0xffffffffu, den1, o);
        den2 += __shfl_xor_sync(0xffffffffu, den2, o);
        den3 += __shfl_xor_sync(0xffffffffu, den3, o);
    }
    float dh = (head == 0) ? den0 : (head == 1) ? den1 : (head == 2) ? den2 : den3;
    float inv = 1.f / (dh + 1e-16f);
    float acc[8];
#pragma unroll
    for (int j = 0; j < 4; j++) {
        float2 f = unpk2(acc2[j]);
        acc[2 * j] = f.x * inv;
        acc[2 * j + 1] = f.y * inv;
    }
#pragma unroll
    for (int j = 0; j < 8; j++) {
        acc[j] += __shfl_xor_sync(0xffffffffu, acc[j], 8);
        acc[j] += __shfl_xor_sync(0xffffffffu, acc[j], 16);
    }
    if (lane < 8) {
#pragma unroll
        for (int j = 0; j < 8; j++) {
            int cc = lane * 8 + j;
            dst64[cc] = 0.25f * acc[j] + bias[cc] + hin[d * 64 + cc];
        }
    }
}

// layers 1,2: plain aggregation, warp per node
__global__ void k_agg(const float* __restrict__ bias,
                      const float* __restrict__ hin, float* __restrict__ hout) {
    __shared__ int   s_src[8][32];
    __shared__ float s_e[8][128];
    int wib = threadIdx.x >> 5;
    int lane = threadIdx.x & 31;
    int d = blockIdx.x * 8 + wib;
    if (d >= N_NODES) return;
    agg_node(d, bias, hin, s_src[wib], s_e[wib], &hout[d * 64], lane);
}

// layer 3: aggregation + fused output MLP (64->64 elu ->32 elu ->8)
__global__ void __launch_bounds__(256) k_agg_mlp(
    const float* __restrict__ bias, const float* __restrict__ hin,
    const float* __restrict__ Wo1, const float* __restrict__ bo1,
    const float* __restrict__ Wo2, const float* __restrict__ bo2,
    const float* __restrict__ Wo3, const float* __restrict__ bo3,
    float* __restrict__ out, int G)
{
    __shared__ float sW1[64 * 64], sW2[64 * 32], sW3[32 * 8];
    __shared__ float sb1[64], sb2[32], sb3[8];
    __shared__ int   s_src[8][32];
    __shared__ float s_e[8][128];
    __shared__ float mh[8][64], mh1[8][64], mh2[8][32];
    for (int i = threadIdx.x; i < 4096; i += 256) sW1[i] = Wo1[i];
    for (int i = threadIdx.x; i < 2048; i += 256) sW2[i] = Wo2[i];
    if (threadIdx.x < 256) sW3[threadIdx.x] = Wo3[threadIdx.x];
    if (threadIdx.x < 64) sb1[threadIdx.x] = bo1[threadIdx.x];
    if (threadIdx.x < 32) sb2[threadIdx.x] = bo2[threadIdx.x];
    if (threadIdx.x < 8) sb3[threadIdx.x] = bo3[threadIdx.x];
    __syncthreads();
    int wib = threadIdx.x >> 5;
    int lane = threadIdx.x & 31;
    int nw = G * 8;
    for (int d = blockIdx.x * 8 + wib; d < N_NODES; d += nw) {
        agg_node(d, bias, hin, s_src[wib], s_e[wib], mh[wib], lane);
        __syncwarp();
        float a0 = sb1[lane], a1 = sb1[lane + 32];
#pragma unroll
        for (int i = 0; i < 64; i++) {
            float xv = mh[wib][i];
            a0 += xv * sW1[i * 64 + lane];
            a1 += xv * sW1[i * 64 + lane + 32];
        }
        mh1[wib][lane] = eluf(a0);
        mh1[wib][lane + 32] = eluf(a1);
        __syncwarp();
        float a = sb2[lane];
#pragma unroll
        for (int i = 0; i < 64; i++) a += mh1[wib][i] * sW2[i * 32 + lane];
        mh2[wib][lane] = eluf(a);
        __syncwarp();
        if (lane < 8) {
            float o = sb3[lane];
#pragma unroll
            for (int i = 0; i < 32; i++) o += mh2[wib][i] * sW3[i * 8 + lane];
            out[d * 8 + lane] = o;
        }
        __syncwarp();
    }
}

// ---------------- launch ----------------
extern "C" void kernel_launch(void* const* d_in, const int* in_sizes, int n_in,
                              void* d_out, int out_size) {
    const float* x      = (const float*)d_in[0];
    const void*  ei     = d_in[1];
    const float* W_enc1 = (const float*)d_in[2];
    const float* b_enc1 = (const float*)d_in[3];
    const float* W_enc2 = (const float*)d_in[4];
    const float* b_enc2 = (const float*)d_in[5];
    const float* W_g[3] = {(const float*)d_in[6],  (const float*)d_in[10], (const float*)d_in[14]};
    const float* as_[3] = {(const float*)d_in[7],  (const float*)d_in[11], (const float*)d_in[15]};
    const float* ad_[3] = {(const float*)d_in[8],  (const float*)d_in[12], (const float*)d_in[16]};
    const float* bg_[3] = {(const float*)d_in[9],  (const float*)d_in[13], (const float*)d_in[17]};
    const float* W_o1 = (const float*)d_in[18];
    const float* b_o1 = (const float*)d_in[19];
    const float* W_o2 = (const float*)d_in[20];
    const float* b_o2 = (const float*)d_in[21];
    const float* W_o3 = (const float*)d_in[22];
    const float* b_o3 = (const float*)d_in[23];
    float* out = (float*)d_out;

    static bool inited = false;
    static cudaStream_t sB;
    static cudaEvent_t evF, evJ;
    static float* hA_p = nullptr;
    static float* hB_p = nullptr;
    static int* deg_p = nullptr;
    if (!inited) {
        cudaStreamCreateWithFlags(&sB, cudaStreamNonBlocking);
        cudaEventCreateWithFlags(&evF, cudaEventDisableTiming);
        cudaEventCreateWithFlags(&evJ, cudaEventDisableTiming);
        cudaGetSymbolAddress((void**)&hA_p, g_hA);
        cudaGetSymbolAddress((void**)&hB_p, g_hB);
        cudaGetSymbolAddress((void**)&deg_p, g_deg);
        inited = true;
    }
    cudaStream_t s0 = 0;

    // fork: side stream runs layer-1 dense work while stream 0 builds CSR
    cudaEventRecord(evF, s0);
    cudaStreamWaitEvent(sB, evF, 0);

    // stream 0: CSR build (4 nodes)
    cudaMemsetAsync(deg_p, 0, (N_NODES + 160) * sizeof(int), s0);
    k_count<<<(N_EDGES + 255) / 256, 256, 0, s0>>>(ei);
    k_scan<<<NB_SCAN, 256, 0, s0>>>();
    k_scatter<<<(TOT_EDGES + 255) / 256, 256, 0, s0>>>(ei);

    dim3 ggrid((N_NODES + 63) / 64, 2);

    // side stream: fused encoder + layer-1 projection + attention coeffs
    k_gemm_enc<<<ggrid, 256, 0, sB>>>(x, W_enc1, b_enc1, W_enc2, b_enc2,
                                      W_g[0], as_[0], ad_[0], hA_p);

    // join
    cudaEventRecord(evJ, sB);
    cudaStreamWaitEvent(s0, evJ, 0);

    k_agg<<<(N_NODES + 7) / 8, 256, 0, s0>>>(bg_[0], hA_p, hB_p);

    k_gemm_att<<<ggrid, 256, 0, s0>>>(hB_p, W_g[1], as_[1], ad_[1]);
    k_agg<<<(N_NODES + 7) / 8, 256, 0, s0>>>(bg_[1], hB_p, hA_p);

    k_gemm_att<<<ggrid, 256, 0, s0>>>(hA_p, W_g[2], as_[2], ad_[2]);
    const int GAGG = 625;
    k_agg_mlp<<<GAGG, 256, 0, s0>>>(bg_[2], hA_p, W_o1, b_o1, W_o2, b_o2,
                                    W_o3, b_o3, out, GAGG);

    (void)in_sizes; (void)n_in; (void)out_size;
}